// round 3
// baseline (speedup 1.0000x reference)
#include <cuda_runtime.h>
#include <math.h>

#define N_CRIT  128
#define N_PAIRS 8128
#define N_TOT   (N_CRIT + N_PAIRS)   // 8256
#define N_VEC4  (N_TOT / 4)          // 2064
#define MIN_W   1e-7f
#define PREP_T  1024

// Effective (constrained) weight vector: [wc_eff (128) | wint_eff (8128)]
__device__ float g_w[N_TOT];
__device__ float g_inv_sum;

// ---------------------------------------------------------------------------
// Prep: apply constraints, build contiguous weight vector, compute 1/sum.
// One block of 1024 threads; pairs distributed flat, (i,j) recovered from the
// pair index by triangle inversion.
// ---------------------------------------------------------------------------
__global__ void __launch_bounds__(PREP_T)
choquet_prep_kernel(const float* __restrict__ wc,
                    const float* __restrict__ wint) {
    __shared__ float s_wc[N_CRIT];
    __shared__ float s_part[PREP_T / 32];
    const int t = threadIdx.x;

    if (t < N_CRIT) {
        float wce = wc[t];
        if (wce < 0.f) wce = MIN_W;
        s_wc[t] = wce;
        g_w[t]  = wce;
    }
    __syncthreads();

    float sum = (t < N_CRIT) ? s_wc[t] : 0.f;

    // Pair p -> (i, j): p = i*(2*N-1-i)/2 + (j-i-1)
    #pragma unroll
    for (int k = 0; k < (N_PAIRS + PREP_T - 1) / PREP_T; k++) {
        const int p = t + k * PREP_T;
        if (p < N_PAIRS) {
            const float disc = sqrtf((float)(65025 - 8 * p));
            int i = (int)((255.0f - disc) * 0.5f);
            int base = i * (2 * N_CRIT - 1 - i) / 2;
            if (base > p)                        { i--; base = i * (2 * N_CRIT - 1 - i) / 2; }
            else if (p - base >= N_CRIT - 1 - i) { i++; base = i * (2 * N_CRIT - 1 - i) / 2; }
            const int j = p - base + i + 1;
            const float lo = fmaxf(-s_wc[i], -s_wc[j]);
            const float v  = fmaxf(wint[p], lo);
            g_w[N_CRIT + p] = v;
            sum += v;
        }
    }

    #pragma unroll
    for (int off = 16; off > 0; off >>= 1)
        sum += __shfl_xor_sync(0xFFFFFFFFu, sum, off);
    if ((t & 31) == 0) s_part[t >> 5] = sum;
    __syncthreads();
    if (t < 32) {
        float v = (t < PREP_T / 32) ? s_part[t] : 0.f;
        #pragma unroll
        for (int off = 16; off > 0; off >>= 1)
            v += __shfl_xor_sync(0xFFFFFFFFu, v, off);
        if (t == 0) g_inv_sum = 1.0f / v;
    }
}

// ---------------------------------------------------------------------------
// GEMV: one warp per TWO rows, interleaved. Single balanced wave:
// 16384 rows / 2 = 8192 warps = 1024 blocks (<= 7 blocks/SM resident).
// Each w-load feeds two FMA chains; two independent x streams for MLP.
// Epilogue: sigmoid(acc * inv_sum - thr).
// ---------------------------------------------------------------------------
__global__ void __launch_bounds__(256)
choquet_gemv_kernel(const float* __restrict__ x,
                    const float* __restrict__ thr,
                    float* __restrict__ out,
                    int rows) {
    const int warp = (blockIdx.x * blockDim.x + threadIdx.x) >> 5;
    const int lane = threadIdx.x & 31;
    const int r0 = warp * 2;
    const int r1 = r0 + 1;
    if (r0 >= rows) return;

    const float4* __restrict__ xa = reinterpret_cast<const float4*>(
        x + (size_t)r0 * N_TOT);
    // If r1 is out of range, alias row 0 (harmless duplicate read, not stored)
    const float4* __restrict__ xb = reinterpret_cast<const float4*>(
        x + (size_t)(r1 < rows ? r1 : r0) * N_TOT);
    const float4* __restrict__ w4 = reinterpret_cast<const float4*>(g_w);

    float accA = 0.f, accB = 0.f;

    // 2064 = 64*32 + 16
    #pragma unroll 4
    for (int i = lane; i < 2048; i += 32) {
        const float4 w = w4[i];
        const float4 a = xa[i];
        const float4 b = xb[i];
        accA = fmaf(a.x, w.x, accA); accB = fmaf(b.x, w.x, accB);
        accA = fmaf(a.y, w.y, accA); accB = fmaf(b.y, w.y, accB);
        accA = fmaf(a.z, w.z, accA); accB = fmaf(b.z, w.z, accB);
        accA = fmaf(a.w, w.w, accA); accB = fmaf(b.w, w.w, accB);
    }
    if (lane < 16) {
        const int i = 2048 + lane;
        const float4 w = w4[i];
        const float4 a = xa[i];
        const float4 b = xb[i];
        accA = fmaf(a.x, w.x, accA); accB = fmaf(b.x, w.x, accB);
        accA = fmaf(a.y, w.y, accA); accB = fmaf(b.y, w.y, accB);
        accA = fmaf(a.z, w.z, accA); accB = fmaf(b.z, w.z, accB);
        accA = fmaf(a.w, w.w, accA); accB = fmaf(b.w, w.w, accB);
    }

    #pragma unroll
    for (int off = 16; off > 0; off >>= 1) {
        accA += __shfl_xor_sync(0xFFFFFFFFu, accA, off);
        accB += __shfl_xor_sync(0xFFFFFFFFu, accB, off);
    }

    if (lane == 0) {
        const float inv = g_inv_sum;
        const float t0  = thr[0];
        const float sA  = fmaf(accA, inv, -t0);
        out[r0] = 1.0f / (1.0f + __expf(-sA));
        if (r1 < rows) {
            const float sB = fmaf(accB, inv, -t0);
            out[r1] = 1.0f / (1.0f + __expf(-sB));
        }
    }
}

extern "C" void kernel_launch(void* const* d_in, const int* in_sizes, int n_in,
                              void* d_out, int out_size) {
    const float* x    = (const float*)d_in[0];
    const float* wc   = (const float*)d_in[1];
    const float* wint = (const float*)d_in[2];
    const float* thr  = (const float*)d_in[3];
    float* out = (float*)d_out;

    const int rows = in_sizes[0] / N_TOT;

    choquet_prep_kernel<<<1, PREP_T>>>(wc, wint);

    // 8 warps/block, 2 rows/warp -> 16 rows per block
    const int blocks = (rows + 15) / 16;
    choquet_gemv_kernel<<<blocks, 256>>>(x, thr, out, rows);
}